// round 10
// baseline (speedup 1.0000x reference)
#include <cuda_runtime.h>
#include <cuda_fp16.h>

#define N_NODES 100000
#define N_EDGES 6400000
#define F_IN 5
#define F_HID 5
#define F_OUT 10
#define TB 256

// __device__ scratch (allocation-free rule).
__device__ __align__(16) uint4 g_x16[N_NODES];   // f16 {x0,x1},{x2,x3},{x4,1.0},{0,0}
__device__ __align__(16) uint4 g_h16[N_NODES];   // f16 {h-.5 lanes},{..},{h4-.5,0},{0,0}
__device__ __align__(32) float g_h[N_NODES][8];  // f32 {h0..h4, deg, 0, 0}
__device__ __align__(16) uint4 g_agg1[N_NODES];  // f16 sums: x lanes + deg
__device__ __align__(16) uint4 g_agg2[N_NODES];  // f16 sums: (h-.5) lanes

__device__ __forceinline__ void pdl_wait()    { asm volatile("griddepcontrol.wait;" ::: "memory"); }
__device__ __forceinline__ void pdl_trigger() { asm volatile("griddepcontrol.launch_dependents;"); }

__device__ __forceinline__ void red_add_v4_f16x2(uint4* p, uint4 v) {
    unsigned long long gp = __cvta_generic_to_global((void*)p);
    asm volatile("red.global.add.noftz.v4.f16x2 [%0], {%1,%2,%3,%4};"
                 :: "l"(gp), "r"(v.x), "r"(v.y), "r"(v.z), "r"(v.w) : "memory");
}

// Table gather: keep in L1 (high reuse across the pass).
__device__ __forceinline__ uint4 ldg_u4_keep(const uint4* p) {
    uint4 v;
    asm volatile("ld.global.nc.L1::evict_last.v4.u32 {%0,%1,%2,%3}, [%4];"
                 : "=r"(v.x), "=r"(v.y), "=r"(v.z), "=r"(v.w)
                 : "l"(__cvta_generic_to_global((const void*)p)));
    return v;
}

// Streaming index load: don't let it evict table lines.
__device__ __forceinline__ int4 ldg_i4_stream(const int4* p) {
    int4 v;
    asm volatile("ld.global.nc.L1::evict_first.v4.s32 {%0,%1,%2,%3}, [%4];"
                 : "=r"(v.x), "=r"(v.y), "=r"(v.z), "=r"(v.w)
                 : "l"(__cvta_generic_to_global((const void*)p)));
    return v;
}

__device__ __forceinline__ float sigmoidf(float z) {
    return 1.0f / (1.0f + __expf(-z));
}

__device__ __forceinline__ unsigned pack2(float a, float b) {
    __half2 h = __floats2half2_rn(a, b);
    return *(unsigned*)&h;
}

// ---------------------------------------------------------------------------
// K0: pack x into f16 red-layout rows; zero g_agg1 (g_agg2 zeroed in k_node1).
__global__ void k_init(const float* __restrict__ x) {
    int i = blockIdx.x * blockDim.x + threadIdx.x;
    if (i < N_NODES) {
        const float* xr = x + i * F_IN;
        float v0 = __ldg(xr), v1 = __ldg(xr + 1), v2 = __ldg(xr + 2),
              v3 = __ldg(xr + 3), v4 = __ldg(xr + 4);
        g_x16[i] = make_uint4(pack2(v0, v1), pack2(v2, v3), pack2(v4, 1.0f), 0u);
        g_agg1[i] = make_uint4(0u, 0u, 0u, 0u);
    }
    pdl_trigger();
}

// ---------------------------------------------------------------------------
// Edge scatter (proven config: flat grid, x4 coarsening) + L1 residency hints.
// PDL preamble: streaming index loads overlap the predecessor's tail.
template <int LAYER>
__global__ void __launch_bounds__(TB) k_edge(const int4* __restrict__ src4,
                                             const int4* __restrict__ dst4) {
    int t = blockIdx.x * TB + threadIdx.x;
    int4 s, d;
    bool act = t < N_EDGES / 4;
    if (act) {
        s = ldg_i4_stream(&src4[t]);   // preamble: independent of upstream
        d = ldg_i4_stream(&dst4[t]);
    }
    pdl_wait();                        // upstream table/agg writes now visible
    if (act) {
        const uint4* tab = (LAYER == 1) ? g_x16 : g_h16;
        uint4* agg = (LAYER == 1) ? g_agg1 : g_agg2;
        uint4 r0 = ldg_u4_keep(&tab[s.x]);
        uint4 r1 = ldg_u4_keep(&tab[s.y]);
        uint4 r2 = ldg_u4_keep(&tab[s.z]);
        uint4 r3 = ldg_u4_keep(&tab[s.w]);
        red_add_v4_f16x2(&agg[d.x], r0);
        red_add_v4_f16x2(&agg[d.y], r1);
        red_add_v4_f16x2(&agg[d.z], r2);
        red_add_v4_f16x2(&agg[d.w], r3);
    }
    pdl_trigger();
}

// ---------------------------------------------------------------------------
// K2: layer-1 node update: h = sigmoid(x@Ws1 + (agg1/deg)@Wn1 + b1).
// Preamble (pre-wait): x loads + g_agg2 zeroing (edge1 never touches either).
__global__ void k_node1(const float* __restrict__ x,
                        const float* __restrict__ Ws, const float* __restrict__ Wn,
                        const float* __restrict__ b) {
    int i = blockIdx.x * blockDim.x + threadIdx.x;
    bool act = i < N_NODES;
    float xv[5];
    if (act) {
        const float* xr = x + i * F_IN;
        xv[0] = __ldg(xr);     xv[1] = __ldg(xr + 1); xv[2] = __ldg(xr + 2);
        xv[3] = __ldg(xr + 3); xv[4] = __ldg(xr + 4);
        g_agg2[i] = make_uint4(0u, 0u, 0u, 0u);
    }
    pdl_wait();                     // g_agg1 (edge1 reds) now visible
    if (act) {
        uint4 au = g_agg1[i];
        float2 p0 = __half22float2(*(__half2*)&au.x);
        float2 p1 = __half22float2(*(__half2*)&au.y);
        float2 p2 = __half22float2(*(__half2*)&au.z);
        float deg = p2.y;
        float inv = 1.0f / fmaxf(deg, 1.0f);
        float hn[5] = {p0.x * inv, p0.y * inv, p1.x * inv, p1.y * inv, p2.x * inv};
        float o[F_HID];
#pragma unroll
        for (int j = 0; j < F_HID; j++) o[j] = b[j];
#pragma unroll
        for (int k = 0; k < F_IN; k++) {
            float xk = xv[k], hk = hn[k];
#pragma unroll
            for (int j = 0; j < F_HID; j++)
                o[j] += xk * __ldg(&Ws[k * F_HID + j]) + hk * __ldg(&Wn[k * F_HID + j]);
        }
#pragma unroll
        for (int j = 0; j < F_HID; j++) o[j] = sigmoidf(o[j]);
        *(float4*)&g_h[i][0] = make_float4(o[0], o[1], o[2], o[3]);
        *(float4*)&g_h[i][4] = make_float4(o[4], deg, 0.f, 0.f);
        g_h16[i] = make_uint4(pack2(o[0] - 0.5f, o[1] - 0.5f),
                              pack2(o[2] - 0.5f, o[3] - 0.5f),
                              pack2(o[4] - 0.5f, 0.f), 0u);
    }
    pdl_trigger();
}

// ---------------------------------------------------------------------------
// K4: layer-2 node update -> out = sigmoid(h@Ws2 + (agg2/deg)@Wn2 + b2).
// Preamble: g_h reads (node1 completed before edge2 triggered -> stable).
__global__ void k_node2(const float* __restrict__ Ws, const float* __restrict__ Wn,
                        const float* __restrict__ b, float* __restrict__ out) {
    int i = blockIdx.x * blockDim.x + threadIdx.x;
    bool act = i < N_NODES;
    float4 ha, hb;
    if (act) {
        ha = *(const float4*)&g_h[i][0];
        hb = *(const float4*)&g_h[i][4];   // .x = h4, .y = deg
    }
    pdl_wait();                     // g_agg2 (edge2 reds) now visible
    if (act) {
        float deg = hb.y;
        uint4 au = g_agg2[i];
        float2 p0 = __half22float2(*(__half2*)&au.x);
        float2 p1 = __half22float2(*(__half2*)&au.y);
        float2 p2 = __half22float2(*(__half2*)&au.z);
        float half_deg = 0.5f * deg;
        float inv = 1.0f / fmaxf(deg, 1.0f);
        float hv[5] = {ha.x, ha.y, ha.z, ha.w, hb.x};
        float hn[5] = {(p0.x + half_deg) * inv, (p0.y + half_deg) * inv,
                       (p1.x + half_deg) * inv, (p1.y + half_deg) * inv,
                       (p2.x + half_deg) * inv};
        float o[F_OUT];
#pragma unroll
        for (int j = 0; j < F_OUT; j++) o[j] = b[j];
#pragma unroll
        for (int k = 0; k < F_HID; k++) {
            float hk = hv[k], nk = hn[k];
#pragma unroll
            for (int j = 0; j < F_OUT; j++)
                o[j] += hk * __ldg(&Ws[k * F_OUT + j]) + nk * __ldg(&Wn[k * F_OUT + j]);
        }
        float* orow = out + i * F_OUT;
#pragma unroll
        for (int j = 0; j < F_OUT; j++) orow[j] = sigmoidf(o[j]);
    }
}

// ---------------------------------------------------------------------------
// Host-side PDL launch helper.
template <typename... Args>
static void launch_pdl(void (*kern)(Args...), int grid, int block, Args... args) {
    cudaLaunchConfig_t cfg = {};
    cfg.gridDim = dim3(grid);
    cfg.blockDim = dim3(block);
    cfg.dynamicSmemBytes = 0;
    cfg.stream = 0;
    cudaLaunchAttribute attr[1];
    attr[0].id = cudaLaunchAttributeProgrammaticStreamSerialization;
    attr[0].val.programmaticStreamSerializationAllowed = 1;
    cfg.attrs = attr;
    cfg.numAttrs = 1;
    cudaLaunchKernelEx(&cfg, kern, args...);
}

extern "C" void kernel_launch(void* const* d_in, const int* in_sizes, int n_in,
                              void* d_out, int out_size) {
    const float* x       = (const float*)d_in[0];
    const int*   src     = (const int*)d_in[1];
    const int*   dst     = (const int*)d_in[2];
    const float* W_self1 = (const float*)d_in[3];
    const float* W_neigh1= (const float*)d_in[4];
    const float* b1      = (const float*)d_in[5];
    const float* W_self2 = (const float*)d_in[6];
    const float* W_neigh2= (const float*)d_in[7];
    const float* b2      = (const float*)d_in[8];
    float* out = (float*)d_out;

    int nb_nodes = (N_NODES + TB - 1) / TB;
    int nb_edge4 = (N_EDGES / 4 + TB - 1) / TB;   // 6250 blocks

    k_init<<<nb_nodes, TB>>>(x);
    launch_pdl(k_edge<1>, nb_edge4, TB, (const int4*)src, (const int4*)dst);
    launch_pdl(k_node1, nb_nodes, TB, x, W_self1, W_neigh1, b1);
    launch_pdl(k_edge<2>, nb_edge4, TB, (const int4*)src, (const int4*)dst);
    launch_pdl(k_node2, nb_nodes, TB, W_self2, W_neigh2, b2, (float*)out);
}

// round 11
// speedup vs baseline: 1.0328x; 1.0328x over previous
#include <cuda_runtime.h>
#include <cuda_fp16.h>

#define N_NODES 100000
#define N_EDGES 6400000
#define F_IN 5
#define F_HID 5
#define F_OUT 10
#define TB 256

// __device__ scratch (allocation-free rule).
// g_x16: f16 {x0,x1},{x2,x3},{x4,1.0},{0,0}
// g_h16: f16 {h0-.5,h1-.5},{h2-.5,h3-.5},{h4-.5,0},{0,deg}  (single h store;
//        layer-2 self-term reconstructs h = lane + 0.5; deg lane reds into an
//        ignored agg2 lane)
__device__ __align__(16) uint4 g_x16[N_NODES];
__device__ __align__(16) uint4 g_h16[N_NODES];
__device__ __align__(16) uint4 g_agg1[N_NODES];  // f16 sums: x lanes + deg
__device__ __align__(16) uint4 g_agg2[N_NODES];  // f16 sums: (h-.5) lanes (+junk deg lane)

__device__ __forceinline__ void pdl_wait()    { asm volatile("griddepcontrol.wait;" ::: "memory"); }
__device__ __forceinline__ void pdl_trigger() { asm volatile("griddepcontrol.launch_dependents;"); }

__device__ __forceinline__ void red_add_v4_f16x2(uint4* p, uint4 v) {
    unsigned long long gp = __cvta_generic_to_global((void*)p);
    asm volatile("red.global.add.noftz.v4.f16x2 [%0], {%1,%2,%3,%4};"
                 :: "l"(gp), "r"(v.x), "r"(v.y), "r"(v.z), "r"(v.w) : "memory");
}

__device__ __forceinline__ uint4 ldg_u4(const uint4* p) {
    uint4 v;
    asm volatile("ld.global.nc.v4.u32 {%0,%1,%2,%3}, [%4];"
                 : "=r"(v.x), "=r"(v.y), "=r"(v.z), "=r"(v.w)
                 : "l"(__cvta_generic_to_global((const void*)p)));
    return v;
}

// Streaming index load: never let it displace table lines.
__device__ __forceinline__ int4 ldg_i4_stream(const int4* p) {
    int4 v;
    asm volatile("ld.global.nc.L1::evict_first.v4.s32 {%0,%1,%2,%3}, [%4];"
                 : "=r"(v.x), "=r"(v.y), "=r"(v.z), "=r"(v.w)
                 : "l"(__cvta_generic_to_global((const void*)p)));
    return v;
}

__device__ __forceinline__ float sigmoidf(float z) {
    return 1.0f / (1.0f + __expf(-z));
}

__device__ __forceinline__ unsigned pack2(float a, float b) {
    __half2 h = __floats2half2_rn(a, b);
    return *(unsigned*)&h;
}

// ---------------------------------------------------------------------------
// K0: pack x into f16 red-layout rows; zero g_agg1 (g_agg2 zeroed in k_node1).
__global__ void k_init(const float* __restrict__ x) {
    int i = blockIdx.x * blockDim.x + threadIdx.x;
    if (i < N_NODES) {
        const float* xr = x + i * F_IN;
        float v0 = __ldg(xr), v1 = __ldg(xr + 1), v2 = __ldg(xr + 2),
              v3 = __ldg(xr + 3), v4 = __ldg(xr + 4);
        g_x16[i] = make_uint4(pack2(v0, v1), pack2(v2, v3), pack2(v4, 1.0f), 0u);
        g_agg1[i] = make_uint4(0u, 0u, 0u, 0u);
    }
    pdl_trigger();
}

// ---------------------------------------------------------------------------
// Edge scatter (proven floor config: flat grid, x4 coarsening).
// PDL preamble: streaming index loads overlap the predecessor's tail.
template <int LAYER>
__global__ void __launch_bounds__(TB) k_edge(const int4* __restrict__ src4,
                                             const int4* __restrict__ dst4) {
    int t = blockIdx.x * TB + threadIdx.x;
    int4 s, d;
    bool act = t < N_EDGES / 4;
    if (act) {
        s = ldg_i4_stream(&src4[t]);   // preamble: independent of upstream
        d = ldg_i4_stream(&dst4[t]);
    }
    pdl_wait();                        // upstream table/agg writes now visible
    if (act) {
        const uint4* tab = (LAYER == 1) ? g_x16 : g_h16;
        uint4* agg = (LAYER == 1) ? g_agg1 : g_agg2;
        uint4 r0 = ldg_u4(&tab[s.x]);
        uint4 r1 = ldg_u4(&tab[s.y]);
        uint4 r2 = ldg_u4(&tab[s.z]);
        uint4 r3 = ldg_u4(&tab[s.w]);
        red_add_v4_f16x2(&agg[d.x], r0);
        red_add_v4_f16x2(&agg[d.y], r1);
        red_add_v4_f16x2(&agg[d.z], r2);
        red_add_v4_f16x2(&agg[d.w], r3);
    }
    pdl_trigger();
}

// ---------------------------------------------------------------------------
// K2: layer-1 node update: h = sigmoid(x@Ws1 + (agg1/deg)@Wn1 + b1).
// Single 16B store: g_h16 row carries (h-0.5) lanes AND deg (f16-exact).
// Preamble (pre-wait): x loads + g_agg2 zeroing (edge1 touches neither).
__global__ void k_node1(const float* __restrict__ x,
                        const float* __restrict__ Ws, const float* __restrict__ Wn,
                        const float* __restrict__ b) {
    int i = blockIdx.x * blockDim.x + threadIdx.x;
    bool act = i < N_NODES;
    float xv[5];
    if (act) {
        const float* xr = x + i * F_IN;
        xv[0] = __ldg(xr);     xv[1] = __ldg(xr + 1); xv[2] = __ldg(xr + 2);
        xv[3] = __ldg(xr + 3); xv[4] = __ldg(xr + 4);
        g_agg2[i] = make_uint4(0u, 0u, 0u, 0u);
    }
    pdl_wait();                     // g_agg1 (edge1 reds) now visible
    if (act) {
        uint4 au = g_agg1[i];
        float2 p0 = __half22float2(*(__half2*)&au.x);
        float2 p1 = __half22float2(*(__half2*)&au.y);
        float2 p2 = __half22float2(*(__half2*)&au.z);
        float deg = p2.y;
        float inv = 1.0f / fmaxf(deg, 1.0f);
        float hn[5] = {p0.x * inv, p0.y * inv, p1.x * inv, p1.y * inv, p2.x * inv};
        float o[F_HID];
#pragma unroll
        for (int j = 0; j < F_HID; j++) o[j] = b[j];
#pragma unroll
        for (int k = 0; k < F_IN; k++) {
            float xk = xv[k], hk = hn[k];
#pragma unroll
            for (int j = 0; j < F_HID; j++)
                o[j] += xk * __ldg(&Ws[k * F_HID + j]) + hk * __ldg(&Wn[k * F_HID + j]);
        }
#pragma unroll
        for (int j = 0; j < F_HID; j++) o[j] = sigmoidf(o[j]);
        g_h16[i] = make_uint4(pack2(o[0] - 0.5f, o[1] - 0.5f),
                              pack2(o[2] - 0.5f, o[3] - 0.5f),
                              pack2(o[4] - 0.5f, 0.f),
                              pack2(0.f, deg));
    }
    pdl_trigger();
}

// ---------------------------------------------------------------------------
// K4: layer-2 node update -> out = sigmoid(h@Ws2 + (agg2/deg)@Wn2 + b2).
// Self h reconstructed from g_h16 lanes (+0.5); deg from lane 7.
// agg2 holds sum(h-0.5); true sum = agg2 + 0.5*deg.
__global__ void k_node2(const float* __restrict__ Ws, const float* __restrict__ Wn,
                        const float* __restrict__ b, float* __restrict__ out) {
    int i = blockIdx.x * blockDim.x + threadIdx.x;
    bool act = i < N_NODES;
    uint4 hw;
    if (act) hw = g_h16[i];          // preamble: stable since node1 finished
    pdl_wait();                      // g_agg2 (edge2 reds) now visible
    if (act) {
        float2 h0 = __half22float2(*(__half2*)&hw.x);
        float2 h1 = __half22float2(*(__half2*)&hw.y);
        float2 h2 = __half22float2(*(__half2*)&hw.z);
        float2 h3 = __half22float2(*(__half2*)&hw.w);
        float deg = h3.y;
        float hv[5] = {h0.x + 0.5f, h0.y + 0.5f, h1.x + 0.5f, h1.y + 0.5f, h2.x + 0.5f};
        uint4 au = g_agg2[i];
        float2 p0 = __half22float2(*(__half2*)&au.x);
        float2 p1 = __half22float2(*(__half2*)&au.y);
        float2 p2 = __half22float2(*(__half2*)&au.z);
        float half_deg = 0.5f * deg;
        float inv = 1.0f / fmaxf(deg, 1.0f);
        float hn[5] = {(p0.x + half_deg) * inv, (p0.y + half_deg) * inv,
                       (p1.x + half_deg) * inv, (p1.y + half_deg) * inv,
                       (p2.x + half_deg) * inv};
        float o[F_OUT];
#pragma unroll
        for (int j = 0; j < F_OUT; j++) o[j] = b[j];
#pragma unroll
        for (int k = 0; k < F_HID; k++) {
            float hk = hv[k], nk = hn[k];
#pragma unroll
            for (int j = 0; j < F_OUT; j++)
                o[j] += hk * __ldg(&Ws[k * F_OUT + j]) + nk * __ldg(&Wn[k * F_OUT + j]);
        }
        // 40B row is 8B-aligned -> five st.global.v2
        float2* orow = (float2*)(out + i * F_OUT);
#pragma unroll
        for (int j = 0; j < F_OUT / 2; j++)
            orow[j] = make_float2(sigmoidf(o[2 * j]), sigmoidf(o[2 * j + 1]));
    }
}

// ---------------------------------------------------------------------------
// Host-side PDL launch helper.
template <typename... Args>
static void launch_pdl(void (*kern)(Args...), int grid, int block, Args... args) {
    cudaLaunchConfig_t cfg = {};
    cfg.gridDim = dim3(grid);
    cfg.blockDim = dim3(block);
    cfg.dynamicSmemBytes = 0;
    cfg.stream = 0;
    cudaLaunchAttribute attr[1];
    attr[0].id = cudaLaunchAttributeProgrammaticStreamSerialization;
    attr[0].val.programmaticStreamSerializationAllowed = 1;
    cfg.attrs = attr;
    cfg.numAttrs = 1;
    cudaLaunchKernelEx(&cfg, kern, args...);
}

extern "C" void kernel_launch(void* const* d_in, const int* in_sizes, int n_in,
                              void* d_out, int out_size) {
    const float* x       = (const float*)d_in[0];
    const int*   src     = (const int*)d_in[1];
    const int*   dst     = (const int*)d_in[2];
    const float* W_self1 = (const float*)d_in[3];
    const float* W_neigh1= (const float*)d_in[4];
    const float* b1      = (const float*)d_in[5];
    const float* W_self2 = (const float*)d_in[6];
    const float* W_neigh2= (const float*)d_in[7];
    const float* b2      = (const float*)d_in[8];
    float* out = (float*)d_out;

    int nb_nodes = (N_NODES + TB - 1) / TB;
    int nb_edge4 = (N_EDGES / 4 + TB - 1) / TB;   // 6250 blocks

    k_init<<<nb_nodes, TB>>>(x);
    launch_pdl(k_edge<1>, nb_edge4, TB, (const int4*)src, (const int4*)dst);
    launch_pdl(k_node1, nb_nodes, TB, x, W_self1, W_neigh1, b1);
    launch_pdl(k_edge<2>, nb_edge4, TB, (const int4*)src, (const int4*)dst);
    launch_pdl(k_node2, nb_nodes, TB, W_self2, W_neigh2, b2, (float*)out);
}